// round 13
// baseline (speedup 1.0000x reference)
#include <cuda_runtime.h>
#include <math.h>

// Problem shape is fixed: N = 16384.
#define N_ELEM  16384
#define TN      256                         // tile dimension (rows=cols=threads)
#define NTILES  (N_ELEM / TN)               // 64
#define NBLOCKS (NTILES * (NTILES + 1) / 2) // 2080 upper-triangle tiles

// Column split per tile-row: 216 cols via MUFU tanh.f16x2, 40 via FMA-pipe poly.
#define MUFU_ITERS 27                       // 27 * 8 = 216 columns
#define POLY_ITERS 20                       // 20 * 2 = 40  columns
#define POLY_BASE  216

typedef unsigned long long ull;
typedef unsigned int uint;

// Scratch for deterministic two-stage reduction (no cudaMalloc allowed).
__device__ float        g_partials[NBLOCKS];
__device__ unsigned int g_arrive = 0;       // reset by last block each launch

// ---- f16x2 helpers ---------------------------------------------------------
__device__ __forceinline__ uint cvt2h(float hi, float lo) {   // pack {lo,hi} f16x2
    uint r; asm("cvt.rn.f16x2.f32 %0, %1, %2;" : "=r"(r) : "f"(hi), "f"(lo)); return r;
}
__device__ __forceinline__ uint hsub2(uint a, uint b) {
    uint r; asm("sub.f16x2 %0, %1, %2;" : "=r"(r) : "r"(a), "r"(b)); return r;
}
__device__ __forceinline__ uint hmul2(uint a, uint b) {
    uint r; asm("mul.f16x2 %0, %1, %2;" : "=r"(r) : "r"(a), "r"(b)); return r;
}
__device__ __forceinline__ uint hadd2(uint a, uint b) {
    uint r; asm("add.f16x2 %0, %1, %2;" : "=r"(r) : "r"(a), "r"(b)); return r;
}
__device__ __forceinline__ uint hfma2(uint a, uint b, uint c) {
    uint r; asm("fma.rn.f16x2 %0, %1, %2, %3;" : "=r"(r) : "r"(a), "r"(b), "r"(c)); return r;
}
__device__ __forceinline__ uint htanh2(uint x) {
    uint r; asm("tanh.approx.f16x2 %0, %1;" : "=r"(r) : "r"(x)); return r;
}
__device__ __forceinline__ void h2_to_f32(float& a, float& b, uint p) {
    asm("{\n\t.reg .b16 l, h;\n\tmov.b32 {l, h}, %2;\n\t"
        "cvt.f32.f16 %0, l;\n\tcvt.f32.f16 %1, h;\n\t}"
        : "=f"(a), "=f"(b) : "r"(p));
}
// ---- f32x2 helpers ---------------------------------------------------------
__device__ __forceinline__ ull pack2(float lo, float hi) {
    ull r; asm("mov.b64 %0, {%1, %2};" : "=l"(r) : "f"(lo), "f"(hi)); return r;
}
__device__ __forceinline__ void unpack2(float& lo, float& hi, ull v) {
    asm("mov.b64 {%0, %1}, %2;" : "=f"(lo), "=f"(hi) : "l"(v));
}
__device__ __forceinline__ ull add2(ull a, ull b) {
    ull r; asm("add.rn.f32x2 %0, %1, %2;" : "=l"(r) : "l"(a), "l"(b)); return r;
}
__device__ __forceinline__ ull mul2(ull a, ull b) {
    ull r; asm("mul.rn.f32x2 %0, %1, %2;" : "=l"(r) : "l"(a), "l"(b)); return r;
}
__device__ __forceinline__ ull fma2(ull a, ull b, ull c) {
    ull r; asm("fma.rn.f32x2 %0, %1, %2, %3;" : "=l"(r) : "l"(a), "l"(b), "l"(c)); return r;
}

// One block = one TN x TN tile (I,J) of the upper triangle (I <= J).
// Per pair: term = (1 + tanh(p_i p_j / 2)) * |t_i - t_j| = 2*sigmoid(p_i p_j)*|d|.
// Tile partial = 0.5*sum(term); diagonal tiles get an extra 0.5.
// 216 columns use MUFU tanh.f16x2 (the proven wall); 40 columns use a
// division-free f32x2 polynomial tanh on the otherwise-idle FMA pipe:
//   q = e^{-|z|} via magic-constant range reduction + deg-4 2^-fr Taylor,
//   tanh(|z|/2) = (1-q) * R(q), R ~ 1/(1+q) (deg-4 Chebyshev of 1/(3+s)).
__global__ __launch_bounds__(TN) void pair_tile_kernel(
    const float* __restrict__ yt, const float* __restrict__ yp,
    float* __restrict__ out)
{
    // f16 column stage (cols 0..255): uint4 group g = packs {th2(2g), ph2(2g), th2(2g+1), ph2(2g+1)}
    __shared__ __align__(16) uint4 sh[TN / 4];
    // f32 poly stage (cols 216..255): spt = -t, spl = p * log2(e)
    __shared__ __align__(8) float spt[2 * POLY_ITERS];
    __shared__ __align__(8) float spl[2 * POLY_ITERS];
    __shared__ float  red[TN / 32];
    __shared__ double dred[TN / 32];
    __shared__ unsigned int is_last;

    // Invert linear triangular block index k -> (I, J), I <= J.
    const int k = blockIdx.x;
    const float disc = 2.0f * (float)NTILES + 1.0f;
    int I = (int)((disc - sqrtf(disc * disc - 8.0f * (float)k)) * 0.5f);
    if (I < 0) I = 0;
    if (I >= NTILES) I = NTILES - 1;
    while (((I + 1) * NTILES - ((I + 1) * I) / 2) <= k) ++I;
    while ((I * NTILES - (I * (I - 1)) / 2) > k) --I;
    const int J = I + (k - (I * NTILES - (I * (I - 1)) / 2));

    const int tid  = threadIdx.x;
    const int lane = tid & 31;
    const int wid  = tid >> 5;

    // Row values for this thread.
    const int ig = I * TN + tid;
    const float ti = yt[ig];
    const float pi = yp[ig];
    const uint ti2   = cvt2h(ti, ti);                 // f16 path
    const uint pih2  = cvt2h(0.5f * pi, 0.5f * pi);
    const ull  tip32 = pack2(ti, ti);                 // poly path
    const ull  pip32 = pack2(pi, pi);

    // Stage f16 columns (all 256).
    if (tid < TN / 2) {
        const float2 tc = *(const float2*)(yt + J * TN + 2 * tid);
        const float2 pc = *(const float2*)(yp + J * TN + 2 * tid);
        const uint th2 = cvt2h(tc.y, tc.x);
        const uint ph2 = cvt2h(0.5f * pc.y, 0.5f * pc.x);
        uint* sw = (uint*)sh;
        const int g = tid >> 1, s = tid & 1;
        sw[4 * g + 2 * s]     = th2;
        sw[4 * g + 2 * s + 1] = ph2;
    }
    // Stage f32 poly columns (216..255).
    if (tid < 2 * POLY_ITERS) {
        const int c = J * TN + POLY_BASE + tid;
        spt[tid] = -yt[c];
        spl[tid] = yp[c] * 1.4426950408889634f;       // p * log2(e)
    }
    __syncthreads();

    // ---- packed constants (poly path) ----
    const ull MAG2  = pack2(12582912.0f, 12582912.0f);   // 1.5 * 2^23
    const ull NMAG2 = pack2(-12582912.0f, -12582912.0f);
    const ull CN1   = pack2(-1.0f, -1.0f);
    const ull C1    = pack2(1.0f, 1.0f);
    const ull C2    = pack2(2.0f, 2.0f);
    // 2^{-fr} Taylor, fr in [-0.5, 0.5]
    const ull E1 = pack2(-0.69314718f, -0.69314718f);
    const ull E2 = pack2( 0.24022651f,  0.24022651f);
    const ull E3 = pack2(-0.05550411f, -0.05550411f);
    const ull E4 = pack2( 0.00961813f,  0.00961813f);
    // R(q) ~ 1/(1+q), Horner in s = 2q-1 (deg-4 Chebyshev of 1/(3+s))
    const ull B0 = pack2( 0.666702f,   0.666702f);
    const ull B1 = pack2(-0.221213f,  -0.221213f);
    const ull B2 = pack2( 0.0734571f,  0.0734571f);
    const ull B3 = pack2(-0.0285706f, -0.0285706f);
    const ull B4 = pack2( 0.00980408f, 0.00980408f);

    // f16-path accumulators (4 A-chains, 4 B-chains; <=27 terms/lane, f16-safe).
    uint Aa = 0u, Ab = 0u, Ac = 0u, Ad = 0u;
    uint Ba = 0u, Bb = 0u, Bc = 0u, Bd = 0u;
    // poly-path accumulators (f32x2).
    ull PA = 0ull, PB = 0ull;

    // f16 body for iteration g (8 columns).
#define F16_BODY(g)                                                         \
    {                                                                       \
        const uint4 w0 = sh[2 * (g)];                                       \
        const uint4 w1 = sh[2 * (g) + 1];                                   \
        const uint ad_a = hsub2(ti2, w0.x) & 0x7FFF7FFFu;                   \
        const uint ad_b = hsub2(ti2, w0.z) & 0x7FFF7FFFu;                   \
        const uint ad_c = hsub2(ti2, w1.x) & 0x7FFF7FFFu;                   \
        const uint ad_d = hsub2(ti2, w1.z) & 0x7FFF7FFFu;                   \
        const uint s_a  = htanh2(hmul2(pih2, w0.y));                        \
        const uint s_b  = htanh2(hmul2(pih2, w0.w));                        \
        const uint s_c  = htanh2(hmul2(pih2, w1.y));                        \
        const uint s_d  = htanh2(hmul2(pih2, w1.w));                        \
        Aa = hfma2(s_a, ad_a, Aa);                                          \
        Ab = hfma2(s_b, ad_b, Ab);                                          \
        Ac = hfma2(s_c, ad_c, Ac);                                          \
        Ad = hfma2(s_d, ad_d, Ad);                                          \
        Ba = hadd2(Ba, ad_a);                                               \
        Bb = hadd2(Bb, ad_b);                                               \
        Bc = hadd2(Bc, ad_c);                                               \
        Bd = hadd2(Bd, ad_d);                                               \
    }

    // Interleaved loop: MUFU work + poly work fill MUFU and FMA pipes together.
    #pragma unroll 4
    for (int g = 0; g < POLY_ITERS; g++) {
        F16_BODY(g)

        // ---- poly pair (cols POLY_BASE+2g, +2g+1), all f32x2 ----
        const ull tpair = *(const ull*)(spt + 2 * g);      // (-t_j, -t_j')
        const ull plpr  = *(const ull*)(spl + 2 * g);      // (pl_j, pl_j')
        const ull tz  = mul2(pip32, plpr);                 // z*log2e (signed)
        const ull at  = tz & 0x7FFFFFFF7FFFFFFFull;        // |t| in [0, ~26.3]
        const ull m2  = add2(at, MAG2);                    // magic round
        const ull nn  = add2(m2, NMAG2);                   // n = round(|t|)
        const ull fr  = fma2(nn, CN1, at);                 // fr = |t|-n in [-.5,.5]
        // 2^{-fr}: deg-4 Horner
        ull P = fma2(E4, fr, E3);
        P = fma2(P, fr, E2);
        P = fma2(P, fr, E1);
        P = fma2(P, fr, C1);
        // 2^{-n} from the magic sum's mantissa bits (low 9 bits of MAG2 are 0)
        float mlo, mhi; unpack2(mlo, mhi, m2);
        const uint slo = 0x3F800000u - (__float_as_uint(mlo) << 23);
        const uint shi = 0x3F800000u - (__float_as_uint(mhi) << 23);
        const ull s2 = pack2(__uint_as_float(slo), __uint_as_float(shi));
        const ull q  = mul2(s2, P);                        // e^{-|z|} in (0,1]
        // R(q) ~ 1/(1+q), Horner in s = 2q-1
        const ull sr = fma2(q, C2, CN1);
        ull R = fma2(B4, sr, B3);
        R = fma2(R, sr, B2);
        R = fma2(R, sr, B1);
        R = fma2(R, sr, B0);
        const ull q1 = fma2(q, CN1, C1);                   // 1-q
        const ull T  = mul2(q1, R);                        // tanh(|z|/2) >= 0
        // d, |d|, sign transfer
        const ull d2  = add2(tip32, tpair);                // t_i - t_j
        const ull ad2 = d2 & 0x7FFFFFFF7FFFFFFFull;
        const ull sd2 = ad2 ^ (tz & 0x8000000080000000ull);// |d| signed by z
        PA = fma2(T, sd2, PA);                             // += tanh*|d|*sgn
        PB = add2(PB, ad2);                                // += |d|
    }
    // Remaining f16-only iterations (cols 160..215).
    #pragma unroll
    for (int g = POLY_ITERS; g < MUFU_ITERS; g++) {
        F16_BODY(g)
    }
#undef F16_BODY

    // Combine: f16 chains -> f32, plus poly f32x2 chains.
    const uint At = hadd2(hadd2(Aa, Ab), hadd2(Ac, Ad));
    const uint Bt = hadd2(hadd2(Ba, Bb), hadd2(Bc, Bd));
    float al, ah, bl, bh;
    h2_to_f32(al, ah, At);
    h2_to_f32(bl, bh, Bt);
    float pal, pah, pbl, pbh;
    unpack2(pal, pah, PA);
    unpack2(pbl, pbh, PB);
    float P = 0.5f * (((al + ah) + (bl + bh)) + ((pal + pah) + (pbl + pbh)));
    if (I == J) P *= 0.5f;

    // Block reduction: warp butterfly + one shared stage.
    #pragma unroll
    for (int o = 16; o > 0; o >>= 1)
        P += __shfl_xor_sync(0xFFFFFFFFu, P, o);
    if (lane == 0) red[wid] = P;
    __syncthreads();

    // Publish partial; last-arriving block does the (deterministic) final sum.
    if (tid == 0) {
        float s = 0.f;
        #pragma unroll
        for (int w = 0; w < TN / 32; w++) s += red[w];
        g_partials[k] = s;
        __threadfence();
        unsigned int old = atomicAdd(&g_arrive, 1u);
        is_last = (old == (unsigned)(NBLOCKS - 1)) ? 1u : 0u;
    }
    __syncthreads();

    if (is_last) {
        __threadfence();
        double s = 0.0;
        for (int i = tid; i < NBLOCKS; i += TN)   // fixed order -> deterministic
            s += (double)g_partials[i];
        #pragma unroll
        for (int o = 16; o > 0; o >>= 1)
            s += __shfl_xor_sync(0xFFFFFFFFu, s, o);
        if (lane == 0) dred[wid] = s;
        __syncthreads();
        if (tid == 0) {
            double tot = 0.0;
            #pragma unroll
            for (int w = 0; w < TN / 32; w++) tot += dred[w];
            const double n2 = (double)N_ELEM * (double)N_ELEM;
            out[0] = (float)(-tot / n2);
            g_arrive = 0;                          // re-arm for next graph replay
        }
    }
}

extern "C" void kernel_launch(void* const* d_in, const int* in_sizes, int n_in,
                              void* d_out, int out_size)
{
    const float* yt = (const float*)d_in[0];  // y_true
    const float* yp = (const float*)d_in[1];  // y_pred
    float* out = (float*)d_out;

    pair_tile_kernel<<<NBLOCKS, TN>>>(yt, yp, out);
}

// round 14
// speedup vs baseline: 1.0969x; 1.0969x over previous
#include <cuda_runtime.h>
#include <math.h>

// Problem shape is fixed: N = 16384.
#define N_ELEM  16384
#define TN      256                         // tile dimension (rows=cols=threads)
#define NTILES  (N_ELEM / TN)               // 64
#define NBLOCKS (NTILES * (NTILES + 1) / 2) // 2080 upper-triangle tiles

// Column split per tile-row: 208 cols MUFU tanh.f16x2, 48 cols FMA-pipe f16x2 poly.
#define F16_ITERS  26                       // 26 * 8 = 208 columns
#define POLY_ITERS 24                       // 24 * 2 = 48  columns
#define POLY_BASE  208

typedef unsigned int uint;

// Scratch for deterministic two-stage reduction (no cudaMalloc allowed).
__device__ float        g_partials[NBLOCKS];
__device__ unsigned int g_arrive = 0;       // reset by last block each launch

// ---- f16x2 helpers ---------------------------------------------------------
__device__ __forceinline__ uint cvt2h(float hi, float lo) {   // pack {lo,hi} f16x2
    uint r; asm("cvt.rn.f16x2.f32 %0, %1, %2;" : "=r"(r) : "f"(hi), "f"(lo)); return r;
}
__device__ __forceinline__ uint hsub2(uint a, uint b) {
    uint r; asm("sub.f16x2 %0, %1, %2;" : "=r"(r) : "r"(a), "r"(b)); return r;
}
__device__ __forceinline__ uint hmul2(uint a, uint b) {
    uint r; asm("mul.f16x2 %0, %1, %2;" : "=r"(r) : "r"(a), "r"(b)); return r;
}
__device__ __forceinline__ uint hadd2(uint a, uint b) {
    uint r; asm("add.f16x2 %0, %1, %2;" : "=r"(r) : "r"(a), "r"(b)); return r;
}
__device__ __forceinline__ uint hfma2(uint a, uint b, uint c) {
    uint r; asm("fma.rn.f16x2 %0, %1, %2, %3;" : "=r"(r) : "r"(a), "r"(b), "r"(c)); return r;
}
__device__ __forceinline__ uint hmin2(uint a, uint b) {
    uint r; asm("min.f16x2 %0, %1, %2;" : "=r"(r) : "r"(a), "r"(b)); return r;
}
__device__ __forceinline__ uint htanh2(uint x) {
    uint r; asm("tanh.approx.f16x2 %0, %1;" : "=r"(r) : "r"(x)); return r;
}
__device__ __forceinline__ void h2_to_f32(float& a, float& b, uint p) {
    asm("{\n\t.reg .b16 l, h;\n\tmov.b32 {l, h}, %2;\n\t"
        "cvt.f32.f16 %0, l;\n\tcvt.f32.f16 %1, h;\n\t}"
        : "=f"(a), "=f"(b) : "r"(p));
}

// ---- packed f16x2 constants (one u32 each) ----
#define MAGH   0x62006200u   // 1536.0 : magic rounder (f16 spacing=1 here)
#define C1548  0x4BBE4BBEu   // 15.484375 : clamp so n <= 15
#define ONEH   0x3C003C00u   // 1.0
#define E1N    0xB98CB98Cu   // -0.693359  2^-x Taylor
#define E2P    0x33B033B0u   //  0.240234
#define E3N    0xAB1BAB1Bu   // -0.055511
#define R0P    0x3BFF3BFFu   //  0.999512  R(q) ~ 1/(1+q), deg-4 Chebyshev
#define R1N    0xBBE3BBE3u   // -0.985840
#define R2P    0x3AFA3AFAu   //  0.872070
#define R3N    0xB857B857u   // -0.542480
#define R4P    0x31053105u   //  0.156860

// One block = one TN x TN tile (I,J) of the upper triangle (I <= J).
// Per pair: term = (1 + tanh(p_i p_j / 2)) * |t_i - t_j| = 2*sigmoid(p_i p_j)*|d|.
// Tile partial = 0.5*sum(term); diagonal tiles get an extra 0.5.
// Cols 0..207: MUFU tanh.f16x2 (the measured wall, 16 elem/cyc/SM).
// Cols 208..255: division-free f16x2 poly tanh on the otherwise-idle FMA pipe:
//   u = |z|*log2e (clamped to 15.48), magic-add 1536 -> n, fr = u - n,
//   q = e^{-|z|} = 2^{-n} (bit-built) * P(fr),  tanh(|z|/2) = (1-q)*R(q).
__global__ __launch_bounds__(TN) void pair_tile_kernel(
    const float* __restrict__ yt, const float* __restrict__ yp,
    float* __restrict__ out)
{
    // f16 column stage (cols 0..207): uint4 group G = packs {th2(2G), ph2(2G), th2(2G+1), ph2(2G+1)}
    __shared__ __align__(16) uint4 sh[2 * F16_ITERS];
    // poly stage (cols 208..255): sp[g] = { t-pack, (p*log2e)-pack } f16x2
    __shared__ __align__(8) uint2 sp[POLY_ITERS];
    __shared__ float  red[TN / 32];
    __shared__ double dred[TN / 32];
    __shared__ unsigned int is_last;

    // Invert linear triangular block index k -> (I, J), I <= J.
    const int k = blockIdx.x;
    const float disc = 2.0f * (float)NTILES + 1.0f;
    int I = (int)((disc - sqrtf(disc * disc - 8.0f * (float)k)) * 0.5f);
    if (I < 0) I = 0;
    if (I >= NTILES) I = NTILES - 1;
    while (((I + 1) * NTILES - ((I + 1) * I) / 2) <= k) ++I;
    while ((I * NTILES - (I * (I - 1)) / 2) > k) --I;
    const int J = I + (k - (I * NTILES - (I * (I - 1)) / 2));

    const int tid  = threadIdx.x;
    const int lane = tid & 31;
    const int wid  = tid >> 5;

    // Row values for this thread.
    const int ig = I * TN + tid;
    const float ti = yt[ig];
    const float pi = yp[ig];
    const uint ti2  = cvt2h(ti, ti);                        // broadcast t_i
    const uint pih2 = cvt2h(0.5f * pi, 0.5f * pi);          // p_i / 2 (MUFU path)
    const float pil = pi * 1.4426950408889634f;
    const uint pil2 = cvt2h(pil, pil);                      // p_i * log2e (poly path)

    // Stage columns.
    if (tid < POLY_BASE / 2) {                              // f16 cols 0..207
        const float2 tc = *(const float2*)(yt + J * TN + 2 * tid);
        const float2 pc = *(const float2*)(yp + J * TN + 2 * tid);
        const uint th2 = cvt2h(tc.y, tc.x);
        const uint ph2 = cvt2h(0.5f * pc.y, 0.5f * pc.x);
        uint* sw = (uint*)sh;
        const int g = tid >> 1, s = tid & 1;
        sw[4 * g + 2 * s]     = th2;
        sw[4 * g + 2 * s + 1] = ph2;
    } else if (tid < POLY_BASE / 2 + POLY_ITERS) {          // poly cols 208..255
        const int idx = tid - POLY_BASE / 2;
        const int c = J * TN + POLY_BASE + 2 * idx;
        const float2 tc = *(const float2*)(yt + c);
        const float2 pc = *(const float2*)(yp + c);
        sp[idx].x = cvt2h(tc.y, tc.x);
        sp[idx].y = cvt2h(pc.y * 1.4426950408889634f,
                          pc.x * 1.4426950408889634f);
    }
    __syncthreads();

    // MUFU-path accumulators (4 A-chains, 4 B-chains; <=26 terms/lane, f16-safe).
    uint Aa = 0u, Ab = 0u, Ac = 0u, Ad = 0u;
    uint Ba = 0u, Bb = 0u, Bc = 0u, Bd = 0u;
    // poly-path accumulators (<=24 terms/lane).
    uint PolyA = 0u, PolyB = 0u;

#define F16_BODY(g)                                                         \
    {                                                                       \
        const uint4 w0 = sh[2 * (g)];                                       \
        const uint4 w1 = sh[2 * (g) + 1];                                   \
        const uint ad_a = hsub2(ti2, w0.x) & 0x7FFF7FFFu;                   \
        const uint ad_b = hsub2(ti2, w0.z) & 0x7FFF7FFFu;                   \
        const uint ad_c = hsub2(ti2, w1.x) & 0x7FFF7FFFu;                   \
        const uint ad_d = hsub2(ti2, w1.z) & 0x7FFF7FFFu;                   \
        const uint s_a  = htanh2(hmul2(pih2, w0.y));                        \
        const uint s_b  = htanh2(hmul2(pih2, w0.w));                        \
        const uint s_c  = htanh2(hmul2(pih2, w1.y));                        \
        const uint s_d  = htanh2(hmul2(pih2, w1.w));                        \
        Aa = hfma2(s_a, ad_a, Aa);                                          \
        Ab = hfma2(s_b, ad_b, Ab);                                          \
        Ac = hfma2(s_c, ad_c, Ac);                                          \
        Ad = hfma2(s_d, ad_d, Ad);                                          \
        Ba = hadd2(Ba, ad_a);                                               \
        Bb = hadd2(Bb, ad_b);                                               \
        Bc = hadd2(Bc, ad_c);                                               \
        Bd = hadd2(Bd, ad_d);                                               \
    }

#define POLY_BODY(g)                                                        \
    {                                                                       \
        const uint2 pp = sp[g];                                             \
        const uint zs  = hmul2(pil2, pp.y);          /* z*log2e, signed */  \
        const uint at  = hmin2(zs & 0x7FFF7FFFu, C1548);                    \
        const uint m2  = hadd2(at, MAGH);            /* int-rounded */      \
        const uint nsh = (m2 & 0x000F000Fu) << 10;                          \
        const uint sb  = 0x3C003C00u - nsh;          /* f16x2 2^{-n} */     \
        const uint nn  = hsub2(m2, MAGH);            /* n as f16 */         \
        const uint fr  = hsub2(at, nn);              /* [-0.5, 0.5] */      \
        uint P = hfma2(E3N, fr, E2P);                                       \
        P = hfma2(P, fr, E1N);                                              \
        P = hfma2(P, fr, ONEH);                      /* 2^{-fr} */          \
        const uint q = hmul2(sb, P);                 /* e^{-|z|} */         \
        uint R = hfma2(R4P, q, R3N);                                        \
        R = hfma2(R, q, R2P);                                               \
        R = hfma2(R, q, R1N);                                               \
        R = hfma2(R, q, R0P);                        /* ~ 1/(1+q) */        \
        const uint T  = hfma2(q ^ 0x80008000u, R, R);/* (1-q)R */           \
        const uint ad = hsub2(ti2, pp.x) & 0x7FFF7FFFu;                     \
        const uint sd = ad ^ (zs & 0x80008000u);     /* |d|*sgn(z) */       \
        PolyA = hfma2(T, sd, PolyA);                                        \
        PolyB = hadd2(PolyB, ad);                                           \
    }

    // Interleaved: MUFU tanh work + FMA-pipe poly work fill both pipes.
    #pragma unroll 4
    for (int g = 0; g < POLY_ITERS; g++) {
        F16_BODY(g)
        POLY_BODY(g)
    }
    #pragma unroll
    for (int g = POLY_ITERS; g < F16_ITERS; g++) {
        F16_BODY(g)
    }
#undef F16_BODY
#undef POLY_BODY

    // Combine all chains -> f32.
    const uint At = hadd2(hadd2(Aa, Ab), hadd2(Ac, Ad));
    const uint Bt = hadd2(hadd2(Ba, Bb), hadd2(Bc, Bd));
    float al, ah, bl, bh, qal, qah, qbl, qbh;
    h2_to_f32(al, ah, At);
    h2_to_f32(bl, bh, Bt);
    h2_to_f32(qal, qah, PolyA);
    h2_to_f32(qbl, qbh, PolyB);
    float P = 0.5f * (((al + ah) + (bl + bh)) + ((qal + qah) + (qbl + qbh)));
    if (I == J) P *= 0.5f;

    // Block reduction: warp butterfly + one shared stage.
    #pragma unroll
    for (int o = 16; o > 0; o >>= 1)
        P += __shfl_xor_sync(0xFFFFFFFFu, P, o);
    if (lane == 0) red[wid] = P;
    __syncthreads();

    // Publish partial; last-arriving block does the (deterministic) final sum.
    if (tid == 0) {
        float s = 0.f;
        #pragma unroll
        for (int w = 0; w < TN / 32; w++) s += red[w];
        g_partials[k] = s;
        __threadfence();
        unsigned int old = atomicAdd(&g_arrive, 1u);
        is_last = (old == (unsigned)(NBLOCKS - 1)) ? 1u : 0u;
    }
    __syncthreads();

    if (is_last) {
        __threadfence();
        double s = 0.0;
        for (int i = tid; i < NBLOCKS; i += TN)   // fixed order -> deterministic
            s += (double)g_partials[i];
        #pragma unroll
        for (int o = 16; o > 0; o >>= 1)
            s += __shfl_xor_sync(0xFFFFFFFFu, s, o);
        if (lane == 0) dred[wid] = s;
        __syncthreads();
        if (tid == 0) {
            double tot = 0.0;
            #pragma unroll
            for (int w = 0; w < TN / 32; w++) tot += dred[w];
            const double n2 = (double)N_ELEM * (double)N_ELEM;
            out[0] = (float)(-tot / n2);
            g_arrive = 0;                          // re-arm for next graph replay
        }
    }
}

extern "C" void kernel_launch(void* const* d_in, const int* in_sizes, int n_in,
                              void* d_out, int out_size)
{
    const float* yt = (const float*)d_in[0];  // y_true
    const float* yp = (const float*)d_in[1];  // y_pred
    float* out = (float*)d_out;

    pair_tile_kernel<<<NBLOCKS, TN>>>(yt, yp, out);
}